// round 14
// baseline (speedup 1.0000x reference)
#include <cuda_runtime.h>
#include <cuda_bf16.h>
#include <cstdint>

// ---------------------------------------------------------------------------
// RWKV7 Tmix forward, B=2 T=2048 C=2048 H=32 N=64   (all-FFMA, proven path)
//   1) mix_kernel   : token shift + 6 lerps (f32)
//   2) rkv_kernel   : r/k/v projections batched (grid.z=3), A-dup smem GEMM
//   3) s1_kernel    : 4 low-rank stage-1 GEMMs fused (tanh/sigmoid epi)
//   4) s2_kernel    : low-rank stage-2 batched (grid.z=4)
//   5) post_kernel  : softplus/sigmoid/kk-norm/k,v update + bf16 staging
//   6) scan_kernel  : sequential delta-rule recurrence (f32x2, LDS.128 loads)
//   7) gn_kernel    : per-head GroupNorm + r.k.r_k bonus + gate
//   8) wo_kernel    : (y*g) @ W_o -> d_out ; tail_kernel: x[:,-1]
// ---------------------------------------------------------------------------

constexpr int B_ = 2, T_ = 2048, C_ = 2048, H_ = 32, N_ = 64;
constexpr int M_ = B_ * T_;                       // 4096 token rows
constexpr size_t BTC_ = (size_t)B_ * T_ * C_;     // 8,388,608

typedef unsigned long long ull;

// ---- scratch: __device__ globals ------------------------------------------
__device__ float g_xr[BTC_], g_xw[BTC_], g_xk[BTC_], g_xv[BTC_], g_xa[BTC_], g_xg[BTC_];
__device__ float g_r[BTC_], g_k[BTC_], g_v[BTC_];
__device__ float g_wout[BTC_], g_aout[BTC_], g_vout[BTC_], g_g[BTC_];
__device__ float g_o[BTC_], g_y[BTC_];
__device__ float g_hw[M_ * 64], g_ha[M_ * 64], g_hv[M_ * 32], g_hg[M_ * 128];
__device__ __nv_bfloat16 sb_r[BTC_], sb_k[BTC_], sb_v[BTC_], sb_w[BTC_], sb_a[BTC_], sb_b[BTC_];

// ---------------------------------------------------------------------------
// packed f32x2 + cp.async helpers
// ---------------------------------------------------------------------------
__device__ __forceinline__ ull pk2dup(float v) {
    ull r; unsigned u = __float_as_uint(v);
    asm("mov.b64 %0, {%1, %2};" : "=l"(r) : "r"(u), "r"(u));
    return r;
}
__device__ __forceinline__ ull pk2(float a, float b) {
    ull r;
    asm("mov.b64 %0, {%1, %2};" : "=l"(r) : "r"(__float_as_uint(a)), "r"(__float_as_uint(b)));
    return r;
}
__device__ __forceinline__ ull ffma2(ull a, ull b, ull c) {
    ull d;
    asm("fma.rn.f32x2 %0, %1, %2, %3;" : "=l"(d) : "l"(a), "l"(b), "l"(c));
    return d;
}
__device__ __forceinline__ ull mul2(ull a, ull b) {
    ull d;
    asm("mul.rn.f32x2 %0, %1, %2;" : "=l"(d) : "l"(a), "l"(b));
    return d;
}
__device__ __forceinline__ ull add2(ull a, ull b) {
    ull d;
    asm("add.rn.f32x2 %0, %1, %2;" : "=l"(d) : "l"(a), "l"(b));
    return d;
}
__device__ __forceinline__ float2 upk2(ull v) {
    unsigned lo, hi;
    asm("mov.b64 {%0, %1}, %2;" : "=r"(lo), "=r"(hi) : "l"(v));
    return make_float2(__uint_as_float(lo), __uint_as_float(hi));
}
__device__ __forceinline__ void cp16(uint32_t s, const void* g) {
    asm volatile("cp.async.cg.shared.global [%0], [%1], 16;" :: "r"(s), "l"(g));
}
__device__ __forceinline__ void cp_commit() { asm volatile("cp.async.commit_group;"); }
__device__ __forceinline__ void cp_wait0()  { asm volatile("cp.async.wait_group 0;"); }

__device__ __forceinline__ float sigm(float x) { return 1.f / (1.f + expf(-x)); }
__device__ __forceinline__ float wredsum(float v) {
#pragma unroll
    for (int o = 16; o; o >>= 1) v += __shfl_xor_sync(0xffffffffu, v, o);
    return v;
}

// ---------------------------------------------------------------------------
// 1) token shift + mixes (vectorized float4)
// ---------------------------------------------------------------------------
__global__ void __launch_bounds__(256) mix_kernel(
    const float4* __restrict__ x4, const float4* __restrict__ sh4,
    const float4* __restrict__ mr, const float4* __restrict__ mw,
    const float4* __restrict__ mk, const float4* __restrict__ mv,
    const float4* __restrict__ ma, const float4* __restrict__ mg)
{
    size_t i = (size_t)blockIdx.x * 256 + threadIdx.x;   // over BTC/4
    int c4 = (int)(i & 511);                              // C/4 = 512
    size_t bt = i >> 9;
    int t = (int)(bt & (T_ - 1));
    float4 xv = x4[i];
    float4 pv = (t == 0) ? sh4[(bt >> 11) * 512 + c4] : x4[i - 512];
    float dx = pv.x - xv.x, dy = pv.y - xv.y, dz = pv.z - xv.z, dw = pv.w - xv.w;
#define MIXOUT(dst, mm) { float4 m = (mm)[c4]; float4 o;                         \
        o.x = fmaf(dx, m.x, xv.x); o.y = fmaf(dy, m.y, xv.y);                    \
        o.z = fmaf(dz, m.z, xv.z); o.w = fmaf(dw, m.w, xv.w);                    \
        ((float4*)(dst))[i] = o; }
    MIXOUT(g_xr, mr) MIXOUT(g_xw, mw) MIXOUT(g_xk, mk)
    MIXOUT(g_xv, mv) MIXOUT(g_xa, ma) MIXOUT(g_xg, mg)
#undef MIXOUT
}

// ---------------------------------------------------------------------------
// GEMM core v3: 128x128 tile, BK=16.
// As: [stage][k][m*2] f32, A values stored DUPLICATED (pairs) so the inner
//     loop's FFMA2 broadcast operand comes straight from one LDS.64 (no MOVs).
//     Filled by LDG->STS.64-dup at tile boundaries (register-staged).
// Bs: [stage][k][n] f32, natural layout, filled by cp.async (double-buffered).
// Inner loop per kk: 8 LDS.64(A) + 2 LDS.128(B) + 32 FFMA2. smem = 48 KB.
// ---------------------------------------------------------------------------
__device__ __forceinline__ void gemm_tile(
    const float* __restrict__ A, const float* __restrict__ Bm,
    float* __restrict__ Cm, int N, int K)
{
    __shared__ __align__(16) float As[2][16][256];   // 32 KB (dup pairs)
    __shared__ __align__(16) float Bs[2][16][128];   // 16 KB

    const int tid  = threadIdx.x;
    // warp-internal: 4 distinct trow, 8 distinct tcol (bijective over 256)
    const int trow = ((tid >> 5) & 3) * 4 + ((tid >> 3) & 3);
    const int tcol = ((tid >> 7) << 3) + (tid & 7);
    const int rowBase = blockIdx.y * 128;
    const int colBase = blockIdx.x * 128;

    const uint32_t sBs = (uint32_t)__cvta_generic_to_shared(Bs);
    const float* Abase = A + (size_t)rowBase * K;
    const float* Bbase = Bm + colBase;

    // A staging coords: thread (am, ah) owns row am, k-half ah (8 values)
    const int am = tid >> 1, ah = tid & 1;
    // B cp.async coords (2 16B chunks per thread per tile)
    const int br0 = tid >> 5,          bc0 = (tid & 31) * 16;
    const int br1 = (tid + 256) >> 5,  bc1 = ((tid + 256) & 31) * 16;

    ull acc[8][4];
#pragma unroll
    for (int i = 0; i < 8; i++)
#pragma unroll
        for (int j = 0; j < 4; j++) acc[i][j] = 0ull;

#define LDGA(kt) { const float* ap = Abase + (size_t)am * K + (kt) + ah * 8;     \
        aq0 = *(const float4*)ap; aq1 = *(const float4*)(ap + 4); }
#define CPB(kt, s) {                                                             \
        cp16(sBs + (s) * 8192 + br0 * 512 + bc0,                                 \
             Bbase + (size_t)((kt) + br0) * N + (bc0 >> 2));                     \
        cp16(sBs + (s) * 8192 + br1 * 512 + bc1,                                 \
             Bbase + (size_t)((kt) + br1) * N + (bc1 >> 2));                     \
        cp_commit(); }
#define STSA(s) { float av[8] = {aq0.x, aq0.y, aq0.z, aq0.w,                     \
                                  aq1.x, aq1.y, aq1.z, aq1.w};                   \
        _Pragma("unroll")                                                        \
        for (int j = 0; j < 8; j++)                                              \
            *(float2*)(&As[s][ah * 8 + j][am * 2]) = make_float2(av[j], av[j]); }

    float4 aq0, aq1;
    const int NT = K / 16;
    LDGA(0)
    CPB(0, 0)
    for (int t = 0; t < NT; t++) {
        cp_wait0();
        __syncthreads();                 // Bs[t&1] ready; prior readers done
        STSA(t & 1)
        if (t + 1 < NT) { LDGA((t + 1) * 16) CPB((t + 1) * 16, (t + 1) & 1) }
        __syncthreads();                 // As[t&1] visible to all
        const int st = t & 1;
#pragma unroll
        for (int kk = 0; kk < 16; kk++) {
            const ull* arow = (const ull*)(As[st][kk]) + trow * 8;
            const ulonglong2* brow = (const ulonglong2*)(Bs[st][kk] + tcol * 8);
            ulonglong2 b01 = brow[0], b23 = brow[1];
#pragma unroll
            for (int i = 0; i < 8; i++) {
                ull ad = arow[i];
                acc[i][0] = ffma2(ad, b01.x, acc[i][0]);
                acc[i][1] = ffma2(ad, b01.y, acc[i][1]);
                acc[i][2] = ffma2(ad, b23.x, acc[i][2]);
                acc[i][3] = ffma2(ad, b23.y, acc[i][3]);
            }
        }
    }
#undef LDGA
#undef CPB
#undef STSA

#pragma unroll
    for (int i = 0; i < 8; i++) {
        float* crow = Cm + (size_t)(rowBase + trow * 8 + i) * N + colBase + tcol * 8;
        float2 v0 = upk2(acc[i][0]), v1 = upk2(acc[i][1]);
        float2 v2 = upk2(acc[i][2]), v3 = upk2(acc[i][3]);
        *(float4*)crow       = make_float4(v0.x, v0.y, v1.x, v1.y);
        *(float4*)(crow + 4) = make_float4(v2.x, v2.y, v3.x, v3.y);
    }
}

// 2) r/k/v projections batched over grid.z
__global__ void __launch_bounds__(256, 2) rkv_kernel(
    const float* __restrict__ Wr, const float* __restrict__ Wk,
    const float* __restrict__ Wv)
{
    const int z = blockIdx.z;
    const float* A = (z == 0) ? g_xr : (z == 1) ? g_xk : g_xv;
    const float* B = (z == 0) ? Wr   : (z == 1) ? Wk   : Wv;
    float*       C = (z == 0) ? g_r  : (z == 1) ? g_k  : g_v;
    gemm_tile(A, B, C, C_, C_);
}

// 4) low-rank stage-2 batched over grid.z
__global__ void __launch_bounds__(256, 2) s2_kernel(
    const float* __restrict__ w2, const float* __restrict__ a2,
    const float* __restrict__ v2, const float* __restrict__ g2)
{
    const int z = blockIdx.z;
    const float* A = (z == 0) ? g_hw   : (z == 1) ? g_ha   : (z == 2) ? g_hv   : g_hg;
    const float* B = (z == 0) ? w2     : (z == 1) ? a2     : (z == 2) ? v2     : g2;
    float*       C = (z == 0) ? g_wout : (z == 1) ? g_aout : (z == 2) ? g_vout : g_g;
    const int    K = (z == 2) ? 32 : (z == 3) ? 128 : 64;
    gemm_tile(A, B, C, C_, K);
}

// 8) output projection
__global__ void __launch_bounds__(256, 2) wo_kernel(
    const float* __restrict__ Wo, float* __restrict__ out)
{
    gemm_tile(g_y, Wo, out, C_, C_);
}

// ---------------------------------------------------------------------------
// 3) fused stage-1 low-rank GEMMs: z selects {w1:tanh, a1, v1, g1:sigmoid}.
//    BM=128, BN=32, BK=16, K=2048. grid (4, M/128, 4); excess x-tiles exit.
// ---------------------------------------------------------------------------
__global__ void __launch_bounds__(256, 2) s1_kernel(
    const float* __restrict__ w1, const float* __restrict__ a1,
    const float* __restrict__ v1, const float* __restrict__ g1)
{
    constexpr int BM = 128, BN = 32, BK = 16, BKP = 20, K = C_;
    const int z = blockIdx.z;
    const int Nz = (z == 2) ? 32 : (z == 3 ? 128 : 64);
    if (blockIdx.x * BN >= Nz) return;

    const float* A  = (z == 0) ? g_xw : (z == 1) ? g_xa : (z == 2) ? g_xv : g_xg;
    const float* Bm = (z == 0) ? w1   : (z == 1) ? a1   : (z == 2) ? v1   : g1;
    float* Cm       = (z == 0) ? g_hw : (z == 1) ? g_ha : (z == 2) ? g_hv : g_hg;

    __shared__ __align__(16) float As[2][BM * BKP];
    __shared__ __align__(16) float Bs[2][BK * BN];

    const int tid  = threadIdx.x;
    const int trow = tid >> 3;       // 0..31 -> 4 rows each
    const int tcol = tid & 7;        // 0..7  -> 4 cols each
    const int rowBase = blockIdx.y * BM;
    const int colBase = blockIdx.x * BN;

    const uint32_t sAs = (uint32_t)__cvta_generic_to_shared(As);
    const uint32_t sBs = (uint32_t)__cvta_generic_to_shared(Bs);
    const int am0 = tid >> 2,         ac0 = (tid & 3) * 4;
    const int am1 = (tid + 256) >> 2, ac1 = ((tid + 256) & 3) * 4;
    const int br = tid >> 3, bc = (tid & 7) * 4;      // tid<128 loads B
    const float* Abase = A + (size_t)rowBase * K;
    const float* Bbase = Bm + colBase;

    ull acc[4][2];
#pragma unroll
    for (int i = 0; i < 4; i++) { acc[i][0] = 0ull; acc[i][1] = 0ull; }

#define LOAD_TILE1(kt, s) {                                                       \
        cp16(sAs + ((s) * BM * BKP + am0 * BKP + ac0) * 4,                        \
             Abase + (size_t)am0 * K + (kt) + ac0);                               \
        cp16(sAs + ((s) * BM * BKP + am1 * BKP + ac1) * 4,                        \
             Abase + (size_t)am1 * K + (kt) + ac1);                               \
        if (tid < 128)                                                            \
            cp16(sBs + ((s) * BK * BN + br * BN + bc) * 4,                        \
                 Bbase + (size_t)((kt) + br) * Nz + bc);                          \
        cp_commit(); }

    const int NT = K / BK;
    LOAD_TILE1(0, 0)
    for (int t = 0; t < NT; t++) {
        cp_wait0();
        __syncthreads();
        if (t + 1 < NT) LOAD_TILE1((t + 1) * BK, (t + 1) & 1)
        const float* as = As[t & 1] + trow * 4 * BKP;
        const float* bs = Bs[t & 1] + tcol * 4;
#pragma unroll
        for (int kk = 0; kk < BK; kk++) {
            const ull* bp = (const ull*)(bs + kk * BN);
            ull b0 = bp[0], b1 = bp[1];
#pragma unroll
            for (int i = 0; i < 4; i++) {
                ull ad = pk2dup(as[i * BKP + kk]);
                acc[i][0] = ffma2(ad, b0, acc[i][0]);
                acc[i][1] = ffma2(ad, b1, acc[i][1]);
            }
        }
        __syncthreads();
    }
#undef LOAD_TILE1

#pragma unroll
    for (int i = 0; i < 4; i++) {
        float* crow = Cm + (size_t)(rowBase + trow * 4 + i) * Nz + colBase + tcol * 4;
        float2 v0 = upk2(acc[i][0]), v1 = upk2(acc[i][1]);
        float4 o = make_float4(v0.x, v0.y, v1.x, v1.y);
        if (z == 0) { o.x = tanhf(o.x); o.y = tanhf(o.y); o.z = tanhf(o.z); o.w = tanhf(o.w); }
        if (z == 3) { o.x = sigm(o.x);  o.y = sigm(o.y);  o.z = sigm(o.z);  o.w = sigm(o.w); }
        *(float4*)crow = o;
    }
}

// ---------------------------------------------------------------------------
// 5) post-GEMM elementwise: one warp per (b,t,h), 2 channels per lane.
// ---------------------------------------------------------------------------
__global__ void __launch_bounds__(256) post_kernel(
    const float* __restrict__ v_first, const float* __restrict__ w0,
    const float* __restrict__ a0, const float* __restrict__ v0,
    const float* __restrict__ kkm, const float* __restrict__ kam)
{
    int g = blockIdx.x * 8 + (threadIdx.x >> 5);          // (b*T+t)*H + h
    int lane = threadIdx.x & 31;
    int h = g & (H_ - 1);
    size_t bt = (size_t)(g >> 5);
    size_t i0 = bt * C_ + (size_t)h * N_ + lane, i1 = i0 + 32;
    int c0 = h * N_ + lane, c1 = c0 + 32;

    float kr0 = g_k[i0], kr1 = g_k[i1];
    float kk0 = kr0 * kkm[c0], kk1 = kr1 * kkm[c1];
    float ss = wredsum(kk0 * kk0 + kk1 * kk1);
    float inv = 1.f / fmaxf(sqrtf(ss), 1e-12f);
    kk0 *= inv; kk1 *= inv;

    float aa0 = sigm(a0[c0] + g_aout[i0]);
    float aa1 = sigm(a0[c1] + g_aout[i1]);

    float z0 = w0[c0] + g_wout[i0], z1 = w0[c1] + g_wout[i1];
    float u0 = -z0, u1 = -z1;
    float sp0 = fmaxf(u0, 0.f) + log1pf(expf(-fabsf(u0)));
    float sp1 = fmaxf(u1, 0.f) + log1pf(expf(-fabsf(u1)));
    float ww0 = -sp0 - 0.5f, ww1 = -sp1 - 0.5f;

    float sv0 = sigm(v0[c0] + g_vout[i0]);
    float sv1 = sigm(v0[c1] + g_vout[i1]);
    float vr0 = g_v[i0], vr1 = g_v[i1];
    float vv0 = fmaf(v_first[i0] - vr0, sv0, vr0);
    float vv1 = fmaf(v_first[i1] - vr1, sv1, vr1);
    g_v[i0] = vv0; g_v[i1] = vv1;

    float kn0 = kr0 * fmaf(aa0 - 1.f, kam[c0], 1.f);
    float kn1 = kr1 * fmaf(aa1 - 1.f, kam[c1], 1.f);
    g_k[i0] = kn0; g_k[i1] = kn1;

    sb_r[i0] = __float2bfloat16(g_r[i0]); sb_r[i1] = __float2bfloat16(g_r[i1]);
    sb_k[i0] = __float2bfloat16(kn0);     sb_k[i1] = __float2bfloat16(kn1);
    sb_v[i0] = __float2bfloat16(vv0);     sb_v[i1] = __float2bfloat16(vv1);
    sb_w[i0] = __float2bfloat16(ww0);     sb_w[i1] = __float2bfloat16(ww1);
    sb_a[i0] = __float2bfloat16(-kk0);    sb_a[i1] = __float2bfloat16(-kk1);
    sb_b[i0] = __float2bfloat16(kk0 * aa0); sb_b[i1] = __float2bfloat16(kk1 * aa1);
}

// ---------------------------------------------------------------------------
// 6) sequential scan, packed f32x2 state, 4-way chains, LDS.128 shared reads.
//    One CTA per (b,h); 128 threads; thread (col, half) owns
//    S[half*32 .. +31][col] as 16 f32x2 pairs.
// ---------------------------------------------------------------------------
__global__ void __launch_bounds__(128) scan_kernel(
    const float* __restrict__ wkv0, float* __restrict__ outS)
{
    const int b = blockIdx.x >> 5;       // H=32
    const int h = blockIdx.x & 31;
    const int tid = threadIdx.x;
    const int col = tid >> 1;
    const int half = tid & 1;
    const int ko = half * 32;

    __shared__ __align__(16) float sh[2][6][N_];   // [buf][r,k,v,ew,a,b][n]

    ull S2[16];
    {
        size_t sbase = (((size_t)b * H_ + h) * N_) * N_;
#pragma unroll
        for (int j = 0; j < 16; j++)
            S2[j] = pk2(wkv0[sbase + (size_t)(ko + 2 * j) * N_ + col],
                        wkv0[sbase + (size_t)(ko + 2 * j + 1) * N_ + col]);
    }

    const size_t base = ((size_t)b * T_) * C_ + (size_t)h * N_;
    float pr = 0, pk = 0, pv = 0, pw = 0, pa = 0, pb = 0;
    if (tid < 64) {
        size_t idx = base + tid;
        pr = __bfloat162float(sb_r[idx]); pk = __bfloat162float(sb_k[idx]);
        pv = __bfloat162float(sb_v[idx]); pw = __bfloat162float(sb_w[idx]);
        pa = __bfloat162float(sb_a[idx]); pb = __bfloat162float(sb_b[idx]);
    }
    int buf = 0;
    for (int t = 0; t < T_; t++) {
        if (tid < 64) {
            sh[buf][0][tid] = pr; sh[buf][1][tid] = pk; sh[buf][2][tid] = pv;
            sh[buf][3][tid] = __expf(pw); sh[buf][4][tid] = pa; sh[buf][5][tid] = pb;
            if (t + 1 < T_) {
                size_t idx = base + (size_t)(t + 1) * C_ + tid;
                pr = __bfloat162float(sb_r[idx]); pk = __bfloat162float(sb_k[idx]);
                pv = __bfloat162float(sb_v[idx]); pw = __bfloat162float(sb_w[idx]);
                pa = __bfloat162float(sb_a[idx]); pb = __bfloat162float(sb_b[idx]);
            }
        }
        __syncthreads();
        const ulonglong2* r4 = (const ulonglong2*)(&sh[buf][0][ko]);
        const ulonglong2* k4 = (const ulonglong2*)(&sh[buf][1][ko]);
        const ulonglong2* e4 = (const ulonglong2*)(&sh[buf][3][ko]);
        const ulonglong2* a4 = (const ulonglong2*)(&sh[buf][4][ko]);
        const ulonglong2* b4 = (const ulonglong2*)(&sh[buf][5][ko]);

        // sa = a . S(col) : 4 independent chains, LDS.128 loads
        ull sc0 = 0ull, sc1 = 0ull, sc2 = 0ull, sc3 = 0ull;
#pragma unroll
        for (int q = 0; q < 8; q += 2) {
            ulonglong2 aA = a4[q], aB = a4[q + 1];
            int j = 2 * q;
            sc0 = ffma2(aA.x, S2[j],     sc0);
            sc1 = ffma2(aA.y, S2[j + 1], sc1);
            sc2 = ffma2(aB.x, S2[j + 2], sc2);
            sc3 = ffma2(aB.y, S2[j + 3], sc3);
        }
        float2 sp = upk2(add2(add2(sc0, sc1), add2(sc2, sc3)));
        float sa = sp.x + sp.y;
        sa += __shfl_xor_sync(0xffffffffu, sa, 1);

        const float vt = sh[buf][2][col];
        const ull sad = pk2dup(sa), vtd = pk2dup(vt);
        ull o0 = 0ull, o1 = 0ull, o2 = 0ull, o3 = 0ull;
#pragma unroll
        for (int q = 0; q < 8; q += 2) {
            ulonglong2 kA = k4[q], kB = k4[q + 1];
            ulonglong2 eA = e4[q], eB = e4[q + 1];
            ulonglong2 bA = b4[q], bB = b4[q + 1];
            ulonglong2 rA = r4[q], rB = r4[q + 1];
            int j = 2 * q;
            ull t0 = ffma2(bA.x, sad, mul2(kA.x, vtd));
            ull t1 = ffma2(bA.y, sad, mul2(kA.y, vtd));
            ull t2 = ffma2(bB.x, sad, mul2(kB.x, vtd));
            ull t3 = ffma2(bB.y, sad, mul2(kB.y, vtd));
            S2[j]     = ffma2(S2[j],     eA.x, t0);
            S2[j + 1] = ffma2(S2[j + 1], eA.y, t1);
            S2[j + 2] = ffma2(S2[j + 2], eB.x, t2);
            S2[j + 3] = ffma2(S2[j + 3], eB.y, t3);
            o0 = ffma2(rA.x, S2[j],     o0);
            o1 = ffma2(rA.y, S2[j + 1], o1);
            o2 = ffma2(rB.x, S2[j + 2], o2);
            o3 = ffma2(rB.y, S2[j + 3], o3);
        }
        float2 op = upk2(add2(add2(o0, o1), add2(o2, o3)));
        float o = op.x + op.y;
        o += __shfl_xor_sync(0xffffffffu, o, 1);
        if (half == 0) g_o[base + (size_t)t * C_ + col] = o;
        buf ^= 1;
    }
    {
        size_t sbase = (((size_t)b * H_ + h) * N_) * N_;
#pragma unroll
        for (int j = 0; j < 16; j++) {
            float2 v = upk2(S2[j]);
            outS[sbase + (size_t)(ko + 2 * j) * N_ + col]     = v.x;
            outS[sbase + (size_t)(ko + 2 * j + 1) * N_ + col] = v.y;
        }
    }
}

// ---------------------------------------------------------------------------
// 7) GroupNorm (per head) + r.k.r_k bonus + gate
// ---------------------------------------------------------------------------
__global__ void __launch_bounds__(256) gn_kernel(
    const float* __restrict__ rk, const float* __restrict__ lnw,
    const float* __restrict__ lnb)
{
    int g = blockIdx.x * 8 + (threadIdx.x >> 5);
    int lane = threadIdx.x & 31;
    int h = g & (H_ - 1);
    size_t bt = (size_t)(g >> 5);
    size_t i0 = bt * C_ + (size_t)h * N_ + lane, i1 = i0 + 32;
    int c0 = h * N_ + lane, c1 = c0 + 32;

    float o0 = g_o[i0], o1 = g_o[i1];
    float mu = wredsum(o0 + o1) * (1.f / 64.f);
    float d0 = o0 - mu, d1 = o1 - mu;
    float var = wredsum(d0 * d0 + d1 * d1) * (1.f / 64.f);
    float inv = 1.f / sqrtf(var + 6.4e-4f);    // EPS_GN = 1e-5 * 8^2
    float y0 = fmaf(d0 * inv, lnw[c0], lnb[c0]);
    float y1 = fmaf(d1 * inv, lnw[c1], lnb[c1]);
    float dot = wredsum(g_r[i0] * g_k[i0] * rk[c0] + g_r[i1] * g_k[i1] * rk[c1]);
    y0 = fmaf(dot, g_v[i0], y0);
    y1 = fmaf(dot, g_v[i1], y1);
    g_y[i0] = y0 * g_g[i0];
    g_y[i1] = y1 * g_g[i1];
}

// 8b) x[:, -1] passthrough
__global__ void tail_kernel(const float* __restrict__ x, float* __restrict__ outx) {
    int i = blockIdx.x * 256 + threadIdx.x;   // B*C = 4096
    int b = i >> 11, c = i & (C_ - 1);
    outx[i] = x[((size_t)b * T_ + (T_ - 1)) * C_ + c];
}

// ---------------------------------------------------------------------------
extern "C" void kernel_launch(void* const* d_in, const int* in_sizes, int n_in,
                              void* d_out, int out_size) {
    const float* x    = (const float*)d_in[0];
    const float* shf  = (const float*)d_in[1];
    const float* wkv0 = (const float*)d_in[2];
    const float* vf   = (const float*)d_in[3];
    const float* mr   = (const float*)d_in[4];
    const float* mw   = (const float*)d_in[5];
    const float* mk   = (const float*)d_in[6];
    const float* mv   = (const float*)d_in[7];
    const float* ma   = (const float*)d_in[8];
    const float* mg   = (const float*)d_in[9];
    const float* w0   = (const float*)d_in[10];
    const float* w1   = (const float*)d_in[11];
    const float* w2   = (const float*)d_in[12];
    const float* a0   = (const float*)d_in[13];
    const float* a1   = (const float*)d_in[14];
    const float* a2   = (const float*)d_in[15];
    const float* v0   = (const float*)d_in[16];
    const float* v1   = (const float*)d_in[17];
    const float* v2   = (const float*)d_in[18];
    const float* g1   = (const float*)d_in[19];
    const float* g2   = (const float*)d_in[20];
    const float* kkm  = (const float*)d_in[21];
    const float* kam  = (const float*)d_in[22];
    const float* rk   = (const float*)d_in[23];
    const float* Wr   = (const float*)d_in[24];
    const float* Wk   = (const float*)d_in[25];
    const float* Wv   = (const float*)d_in[26];
    const float* Wo   = (const float*)d_in[27];
    const float* lnw  = (const float*)d_in[28];
    const float* lnb  = (const float*)d_in[29];

    float* out   = (float*)d_out;                 // [B,T,C]
    float* out_x = out + BTC_;                    // [B,C]
    float* out_S = out_x + (size_t)B_ * C_;       // [B,H,N,N]

    // 1) token shift + mixes
    mix_kernel<<<(unsigned)(BTC_ / 4 / 256), 256>>>(
        (const float4*)x, (const float4*)shf,
        (const float4*)mr, (const float4*)mw, (const float4*)mk,
        (const float4*)mv, (const float4*)ma, (const float4*)mg);

    // 2) big projections r/k/v, batched
    rkv_kernel<<<dim3(C_ / 128, M_ / 128, 3), 256>>>(Wr, Wk, Wv);

    // 3) fused low-rank stage 1 (w1:tanh, a1, v1, g1:sigmoid)
    s1_kernel<<<dim3(4, M_ / 128, 4), 256>>>(w1, a1, v1, g1);

    // 4) low-rank stage 2, batched
    s2_kernel<<<dim3(C_ / 128, M_ / 128, 4), 256>>>(w2, a2, v2, g2);

    // 5) elementwise post + bf16 staging
    post_kernel<<<(B_ * T_ * H_) / 8, 256>>>(vf, w0, a0, v0, kkm, kam);

    // 6) recurrence (also writes final state to d_out)
    scan_kernel<<<B_ * H_, 128>>>(wkv0, out_S);

    // 7) GroupNorm + bonus + gate
    gn_kernel<<<(B_ * T_ * H_) / 8, 256>>>(rk, lnw, lnb);

    // 8) output projection straight into d_out + x[:, -1]
    wo_kernel<<<dim3(C_ / 128, M_ / 128), 256>>>(Wo, out);
    tail_kernel<<<(B_ * C_) / 256, 256>>>(x, out_x);
}